// round 2
// baseline (speedup 1.0000x reference)
#include <cuda_runtime.h>
#include <math.h>

// ---------------------------------------------------------------------------
// Problem constants
// ---------------------------------------------------------------------------
constexpr int kB  = 32, kC = 3, kH = 224, kW = 224;
constexpr int kHW = kH * kW;          // 50176
constexpr int kS  = 256, kD = 768, kL = 12, kNH = 12, kHD = 64;
constexpr int kMLP = 3072, kNC = 1000;
constexpr int kN  = kS + 1;           // 257 tokens
constexpr int kM  = kB * kN;          // 8224 rows
constexpr int kQKV = 3 * kD;          // 2304

// ---------------------------------------------------------------------------
// Scratch (static device globals -- allowed; runtime allocation is not)
// ---------------------------------------------------------------------------
__device__ float g_x[kM * kD];
__device__ float g_h[kM * kD];
__device__ float g_qkv[kM * kQKV];
__device__ float g_att[kM * kD];
__device__ float g_mlp[kM * kMLP];
__device__ float g_seg[kB * kS * kC];
__device__ float g_cls[kB * kD];

// ---------------------------------------------------------------------------
// Helpers
// ---------------------------------------------------------------------------
__device__ __forceinline__ unsigned f2tf32(float f) {
    unsigned u;
    asm("cvt.rna.tf32.f32 %0, %1;" : "=r"(u) : "f"(f));
    return u;
}

__device__ __forceinline__ float gelu_exact(float x) {
    return 0.5f * x * (1.0f + erff(x * 0.70710678118654752440f));
}

__device__ __forceinline__ void mma_tf32(float c[4], const unsigned a[4], const unsigned b[2]) {
    asm volatile(
        "mma.sync.aligned.m16n8k8.row.col.f32.tf32.tf32.f32 "
        "{%0,%1,%2,%3}, {%4,%5,%6,%7}, {%8,%9}, {%0,%1,%2,%3};\n"
        : "+f"(c[0]), "+f"(c[1]), "+f"(c[2]), "+f"(c[3])
        : "r"(a[0]), "r"(a[1]), "r"(a[2]), "r"(a[3]), "r"(b[0]), "r"(b[1]));
}

// ---------------------------------------------------------------------------
// 1) Superpixel segment sums: one block per batch image, smem histogram
// ---------------------------------------------------------------------------
__global__ void seg_sum_kernel(const float* __restrict__ img, const int* __restrict__ seg) {
    __shared__ float sm[kS * kC];
    const int b = blockIdx.x;
    for (int i = threadIdx.x; i < kS * kC; i += blockDim.x) sm[i] = 0.f;
    __syncthreads();
    const int*   sb = seg + (size_t)b * kHW;
    const float* i0 = img + (size_t)(b * kC + 0) * kHW;
    const float* i1 = img + (size_t)(b * kC + 1) * kHW;
    const float* i2 = img + (size_t)(b * kC + 2) * kHW;
    for (int p = threadIdx.x; p < kHW; p += blockDim.x) {
        int s = sb[p];
        atomicAdd(&sm[s * 3 + 0], i0[p]);
        atomicAdd(&sm[s * 3 + 1], i1[p]);
        atomicAdd(&sm[s * 3 + 2], i2[p]);
    }
    __syncthreads();
    for (int i = threadIdx.x; i < kS * kC; i += blockDim.x) g_seg[b * kS * kC + i] = sm[i];
}

// ---------------------------------------------------------------------------
// 2) Build x = concat(cls, seg_mean @ w_fe + b_fe) + pos_embed
// ---------------------------------------------------------------------------
__global__ void embed_kernel(const float* __restrict__ w_fe, const float* __restrict__ b_fe,
                             const float* __restrict__ cls_t, const float* __restrict__ pos) {
    const int tok = blockIdx.x;
    const int b = tok / kN, n = tok % kN;
    float s0 = 0.f, s1 = 0.f, s2 = 0.f;
    if (n > 0) {
        const float* sp = g_seg + (size_t)(b * kS + (n - 1)) * 3;
        const float inv = 1.0f / (float)kHW;
        s0 = sp[0] * inv; s1 = sp[1] * inv; s2 = sp[2] * inv;
    }
    float* xr = g_x + (size_t)tok * kD;
    for (int d = threadIdx.x; d < kD; d += blockDim.x) {
        float pv = pos[n * kD + d];
        float v;
        if (n == 0) v = cls_t[d] + pv;
        else        v = b_fe[d] + pv + s0 * w_fe[d] + s1 * w_fe[kD + d] + s2 * w_fe[2 * kD + d];
        xr[d] = v;
    }
}

// ---------------------------------------------------------------------------
// 3) LayerNorm (one block per row, D=768, 256 threads x 3 elems)
// ---------------------------------------------------------------------------
__global__ __launch_bounds__(256) void ln_kernel(const float* __restrict__ x, float* __restrict__ y,
                          const float* __restrict__ gw, const float* __restrict__ bw,
                          long xstride, long ystride) {
    const int row = blockIdx.x;
    const float* xr = x + (long)row * xstride;
    float*       yr = y + (long)row * ystride;
    const int tid = threadIdx.x;
    float v0 = xr[tid], v1 = xr[tid + 256], v2 = xr[tid + 512];
    __shared__ float red[8];

    float s = v0 + v1 + v2;
    #pragma unroll
    for (int o = 16; o > 0; o >>= 1) s += __shfl_down_sync(0xffffffffu, s, o);
    if ((tid & 31) == 0) red[tid >> 5] = s;
    __syncthreads();
    if (tid < 8) {
        float t = red[tid];
        #pragma unroll
        for (int o = 4; o > 0; o >>= 1) t += __shfl_down_sync(0xffu, t, o);
        if (tid == 0) red[0] = t;
    }
    __syncthreads();
    const float m = red[0] * (1.0f / kD);
    __syncthreads();

    const float d0 = v0 - m, d1 = v1 - m, d2 = v2 - m;
    float q = d0 * d0 + d1 * d1 + d2 * d2;
    #pragma unroll
    for (int o = 16; o > 0; o >>= 1) q += __shfl_down_sync(0xffffffffu, q, o);
    if ((tid & 31) == 0) red[tid >> 5] = q;
    __syncthreads();
    if (tid < 8) {
        float t = red[tid];
        #pragma unroll
        for (int o = 4; o > 0; o >>= 1) t += __shfl_down_sync(0xffu, t, o);
        if (tid == 0) red[0] = t;
    }
    __syncthreads();
    const float inv = rsqrtf(red[0] * (1.0f / kD) + 1e-6f);

    yr[tid]       = d0 * inv * gw[tid]       + bw[tid];
    yr[tid + 256] = d1 * inv * gw[tid + 256] + bw[tid + 256];
    yr[tid + 512] = d2 * inv * gw[tid + 512] + bw[tid + 512];
}

// ---------------------------------------------------------------------------
// 4) Split-tf32 GEMM: C = epilogue(A[M,K] @ W[K,N] + bias [, +res | gelu])
//    BM=BN=128, BK=32, 256 threads, warp tile 32x64, m16n8k8.tf32, hi/lo split
// ---------------------------------------------------------------------------
constexpr int GEMM_SMEM = (2 * 128 * 36 + 2 * 32 * 136) * 4;  // 71680 B

template <int OP>   // 0: +bias   1: +bias, gelu   2: +bias, +res
__global__ __launch_bounds__(256) void gemm_kernel(
    const float* __restrict__ A, const float* __restrict__ Wm,
    const float* __restrict__ bias, const float* __restrict__ res,
    float* __restrict__ Cout, int M, int N, int K)
{
    extern __shared__ unsigned smemu[];
    unsigned* Ah = smemu;               // [128][36]
    unsigned* Al = Ah + 128 * 36;
    unsigned* Bh = Al + 128 * 36;       // [32][136]
    unsigned* Bl = Bh + 32 * 136;

    const int tid = threadIdx.x;
    const int wid = tid >> 5, lane = tid & 31;
    const int gp = lane >> 2, tg = lane & 3;
    const int wm = (wid >> 1) * 32;     // 4 warps along M
    const int wn = (wid & 1) * 64;      // 2 warps along N
    const int m0 = blockIdx.y * 128;
    const int n0 = blockIdx.x * 128;

    float c[2][8][4];
    #pragma unroll
    for (int i = 0; i < 2; i++)
        #pragma unroll
        for (int j = 0; j < 8; j++)
            #pragma unroll
            for (int r = 0; r < 4; r++) c[i][j][r] = 0.f;

    const int arow = tid >> 3, acol = (tid & 7) * 4;
    const int wrow = tid >> 5, wcol = (tid & 31) * 4;

    for (int k0 = 0; k0 < K; k0 += 32) {
        __syncthreads();
        #pragma unroll
        for (int p = 0; p < 4; p++) {
            const int r = p * 32 + arow;
            const int grow = m0 + r;
            float4 v = make_float4(0.f, 0.f, 0.f, 0.f);
            if (grow < M) v = *(const float4*)(A + (size_t)grow * K + k0 + acol);
            float vv[4] = {v.x, v.y, v.z, v.w};
            #pragma unroll
            for (int i = 0; i < 4; i++) {
                unsigned hi = f2tf32(vv[i]);
                Ah[r * 36 + acol + i] = hi;
                Al[r * 36 + acol + i] = f2tf32(vv[i] - __uint_as_float(hi));
            }
        }
        #pragma unroll
        for (int p = 0; p < 4; p++) {
            const int r = p * 8 + wrow;
            float4 v = *(const float4*)(Wm + (size_t)(k0 + r) * N + n0 + wcol);
            float vv[4] = {v.x, v.y, v.z, v.w};
            #pragma unroll
            for (int i = 0; i < 4; i++) {
                unsigned hi = f2tf32(vv[i]);
                Bh[r * 136 + wcol + i] = hi;
                Bl[r * 136 + wcol + i] = f2tf32(vv[i] - __uint_as_float(hi));
            }
        }
        __syncthreads();
        #pragma unroll
        for (int kk = 0; kk < 4; kk++) {
            unsigned ah[2][4], al[2][4], bf[8][2];
            #pragma unroll
            for (int mi = 0; mi < 2; mi++) {
                const int rb = wm + mi * 16;
                const int kc = kk * 8 + tg;
                ah[mi][0] = Ah[(rb + gp) * 36 + kc];
                ah[mi][1] = Ah[(rb + gp + 8) * 36 + kc];
                ah[mi][2] = Ah[(rb + gp) * 36 + kc + 4];
                ah[mi][3] = Ah[(rb + gp + 8) * 36 + kc + 4];
                al[mi][0] = Al[(rb + gp) * 36 + kc];
                al[mi][1] = Al[(rb + gp + 8) * 36 + kc];
                al[mi][2] = Al[(rb + gp) * 36 + kc + 4];
                al[mi][3] = Al[(rb + gp + 8) * 36 + kc + 4];
            }
            #pragma unroll
            for (int ni = 0; ni < 8; ni++) {
                bf[ni][0] = Bh[(kk * 8 + tg) * 136 + wn + ni * 8 + gp];
                bf[ni][1] = Bh[(kk * 8 + tg + 4) * 136 + wn + ni * 8 + gp];
            }
            #pragma unroll
            for (int mi = 0; mi < 2; mi++)
                #pragma unroll
                for (int ni = 0; ni < 8; ni++) {
                    mma_tf32(c[mi][ni], ah[mi], bf[ni]);
                    mma_tf32(c[mi][ni], al[mi], bf[ni]);
                }
            #pragma unroll
            for (int ni = 0; ni < 8; ni++) {
                bf[ni][0] = Bl[(kk * 8 + tg) * 136 + wn + ni * 8 + gp];
                bf[ni][1] = Bl[(kk * 8 + tg + 4) * 136 + wn + ni * 8 + gp];
            }
            #pragma unroll
            for (int mi = 0; mi < 2; mi++)
                #pragma unroll
                for (int ni = 0; ni < 8; ni++)
                    mma_tf32(c[mi][ni], ah[mi], bf[ni]);
        }
    }

    #pragma unroll
    for (int mi = 0; mi < 2; mi++)
        #pragma unroll
        for (int ni = 0; ni < 8; ni++) {
            const int col = n0 + wn + ni * 8 + tg * 2;
            const float b0 = bias[col], b1 = bias[col + 1];
            #pragma unroll
            for (int hh = 0; hh < 2; hh++) {
                const int row = m0 + wm + mi * 16 + gp + hh * 8;
                if (row < M) {
                    float v0 = c[mi][ni][hh * 2 + 0] + b0;
                    float v1 = c[mi][ni][hh * 2 + 1] + b1;
                    if (OP == 1) { v0 = gelu_exact(v0); v1 = gelu_exact(v1); }
                    if (OP == 2) {
                        float2 rr = *(const float2*)(res + (size_t)row * N + col);
                        v0 += rr.x; v1 += rr.y;
                    }
                    *(float2*)(Cout + (size_t)row * N + col) = make_float2(v0, v1);
                }
            }
        }
}

// ---------------------------------------------------------------------------
// 5) Fused attention: one block per (b, head). K,V in smem; online softmax.
// ---------------------------------------------------------------------------
constexpr int ATTN_SMEM = (2 * 257 * 65 + 8 * 64) * 4;  // 135688 B

__global__ __launch_bounds__(256) void attn_kernel() {
    extern __shared__ float sm[];
    float* Ks = sm;                     // [257][65]
    float* Vs = sm + 257 * 65;          // [257][65]
    float* qs = sm + 2 * 257 * 65;      // [8][64]

    const int b = blockIdx.x / kNH, hh = blockIdx.x % kNH;
    const int tid = threadIdx.x, w = tid >> 5, lane = tid & 31;
    const float* base = g_qkv + (size_t)b * kN * kQKV + hh * kHD;

    for (int i = tid; i < kN * kHD; i += 256) {
        const int n = i >> 6, d = i & 63;
        Ks[n * 65 + d] = base[(size_t)n * kQKV + kD + d];
        Vs[n * 65 + d] = base[(size_t)n * kQKV + 2 * kD + d];
    }
    __syncthreads();

    for (int r = w; r < kN; r += 8) {
        qs[w * 64 + lane]      = base[(size_t)r * kQKV + lane];
        qs[w * 64 + lane + 32] = base[(size_t)r * kQKV + lane + 32];
        __syncwarp();
        float q[64];
        #pragma unroll
        for (int k = 0; k < 64; k++) q[k] = qs[w * 64 + k];
        __syncwarp();

        float sc[9];
        #pragma unroll
        for (int t = 0; t < 9; t++) {
            const int j = t * 32 + lane;
            const int jj = (j < kN) ? j : 0;
            float acc = 0.f;
            #pragma unroll
            for (int k = 0; k < 64; k++) acc += q[k] * Ks[jj * 65 + k];
            sc[t] = (j < kN) ? acc * 0.125f : -__int_as_float(0x7f800000);
        }
        float mx = sc[0];
        #pragma unroll
        for (int t = 1; t < 9; t++) mx = fmaxf(mx, sc[t]);
        #pragma unroll
        for (int o = 16; o > 0; o >>= 1) mx = fmaxf(mx, __shfl_xor_sync(0xffffffffu, mx, o));
        float sum = 0.f;
        #pragma unroll
        for (int t = 0; t < 9; t++) { sc[t] = expf(sc[t] - mx); sum += sc[t]; }
        #pragma unroll
        for (int o = 16; o > 0; o >>= 1) sum += __shfl_xor_sync(0xffffffffu, sum, o);
        const float inv = 1.0f / sum;
        #pragma unroll
        for (int t = 0; t < 9; t++) sc[t] *= inv;

        float a0 = 0.f, a1 = 0.f;
        #pragma unroll
        for (int t = 0; t < 9; t++) {
            const int lim = (t == 8) ? 1 : 32;
            #pragma unroll
            for (int s2 = 0; s2 < 32; s2++) {
                if (s2 >= lim) break;
                const float pv = __shfl_sync(0xffffffffu, sc[t], s2);
                const int j = t * 32 + s2;
                a0 += pv * Vs[j * 65 + lane];
                a1 += pv * Vs[j * 65 + 32 + lane];
            }
        }
        float* orow = g_att + (size_t)(b * kN + r) * kD + hh * kHD;
        orow[lane]      = a0;
        orow[lane + 32] = a1;
    }
}

// ---------------------------------------------------------------------------
// 6) Head: out[b, c] = cls_ln[b] . head_w[:, c] + head_b[c]
// ---------------------------------------------------------------------------
__global__ void head_kernel(const float* __restrict__ hw, const float* __restrict__ hb,
                            float* __restrict__ out) {
    __shared__ float xs[kD];
    const int b = blockIdx.y;
    const int col = blockIdx.x * 256 + threadIdx.x;
    for (int i = threadIdx.x; i < kD; i += 256) xs[i] = g_cls[b * kD + i];
    __syncthreads();
    if (col < kNC) {
        float acc = hb[col];
        #pragma unroll 4
        for (int k = 0; k < kD; k++) acc += xs[k] * hw[(size_t)k * kNC + col];
        out[(size_t)b * kNC + col] = acc;
    }
}

// ---------------------------------------------------------------------------
// Launch
// ---------------------------------------------------------------------------
extern "C" void kernel_launch(void* const* d_in, const int* in_sizes, int n_in,
                              void* d_out, int out_size) {
    const float* img    = (const float*)d_in[0];
    const int*   seg    = (const int*)  d_in[1];
    const float* w_fe   = (const float*)d_in[2];
    const float* b_fe   = (const float*)d_in[3];
    const float* cls_t  = (const float*)d_in[4];
    const float* pos    = (const float*)d_in[5];
    const float* ln1_g  = (const float*)d_in[6];
    const float* ln1_b  = (const float*)d_in[7];
    const float* qkv_w  = (const float*)d_in[8];
    const float* qkv_b  = (const float*)d_in[9];
    const float* proj_w = (const float*)d_in[10];
    const float* proj_b = (const float*)d_in[11];
    const float* ln2_g  = (const float*)d_in[12];
    const float* ln2_b  = (const float*)d_in[13];
    const float* mlp_w1 = (const float*)d_in[14];
    const float* mlp_b1 = (const float*)d_in[15];
    const float* mlp_w2 = (const float*)d_in[16];
    const float* mlp_b2 = (const float*)d_in[17];
    const float* norm_g = (const float*)d_in[18];
    const float* norm_b = (const float*)d_in[19];
    const float* head_w = (const float*)d_in[20];
    const float* head_b = (const float*)d_in[21];

    cudaFuncSetAttribute(attn_kernel,    cudaFuncAttributeMaxDynamicSharedMemorySize, ATTN_SMEM);
    cudaFuncSetAttribute(gemm_kernel<0>, cudaFuncAttributeMaxDynamicSharedMemorySize, GEMM_SMEM);
    cudaFuncSetAttribute(gemm_kernel<1>, cudaFuncAttributeMaxDynamicSharedMemorySize, GEMM_SMEM);
    cudaFuncSetAttribute(gemm_kernel<2>, cudaFuncAttributeMaxDynamicSharedMemorySize, GEMM_SMEM);

    float *px, *ph, *pq, *pa, *pm, *pc;
    cudaGetSymbolAddress((void**)&px, g_x);
    cudaGetSymbolAddress((void**)&ph, g_h);
    cudaGetSymbolAddress((void**)&pq, g_qkv);
    cudaGetSymbolAddress((void**)&pa, g_att);
    cudaGetSymbolAddress((void**)&pm, g_mlp);
    cudaGetSymbolAddress((void**)&pc, g_cls);

    seg_sum_kernel<<<kB, 256>>>(img, seg);
    embed_kernel<<<kM, 256>>>(w_fe, b_fe, cls_t, pos);

    const dim3 gQKV(kQKV / 128, (kM + 127) / 128);
    const dim3 gD  (kD   / 128, (kM + 127) / 128);
    const dim3 gMLP(kMLP / 128, (kM + 127) / 128);

    for (int l = 0; l < kL; l++) {
        ln_kernel<<<kM, 256>>>(px, ph, ln1_g + (size_t)l * kD, ln1_b + (size_t)l * kD, kD, kD);
        gemm_kernel<0><<<gQKV, 256, GEMM_SMEM>>>(ph, qkv_w + (size_t)l * kD * kQKV,
                                                 qkv_b + (size_t)l * kQKV, nullptr, pq,
                                                 kM, kQKV, kD);
        attn_kernel<<<kB * kNH, 256, ATTN_SMEM>>>();
        gemm_kernel<2><<<gD, 256, GEMM_SMEM>>>(pa, proj_w + (size_t)l * kD * kD,
                                               proj_b + (size_t)l * kD, px, px,
                                               kM, kD, kD);
        ln_kernel<<<kM, 256>>>(px, ph, ln2_g + (size_t)l * kD, ln2_b + (size_t)l * kD, kD, kD);
        gemm_kernel<1><<<gMLP, 256, GEMM_SMEM>>>(ph, mlp_w1 + (size_t)l * kD * kMLP,
                                                 mlp_b1 + (size_t)l * kMLP, nullptr, pm,
                                                 kM, kMLP, kD);
        gemm_kernel<2><<<gD, 256, GEMM_SMEM>>>(pm, mlp_w2 + (size_t)l * kMLP * kD,
                                               mlp_b2 + (size_t)l * kD, px, px,
                                               kM, kD, kMLP);
    }

    // Final LN on cls rows only (row b lives at x + b*257*768), then head.
    ln_kernel<<<kB, 256>>>(px, pc, norm_g, norm_b, (long)kN * kD, (long)kD);
    head_kernel<<<dim3((kNC + 255) / 256, kB), 256>>>(head_w, head_b, (float*)d_out);
}

// round 5
// speedup vs baseline: 1.4600x; 1.4600x over previous
#include <cuda_runtime.h>
#include <cuda_bf16.h>
#include <math.h>

// ---------------------------------------------------------------------------
// Problem constants
// ---------------------------------------------------------------------------
constexpr int kB  = 32, kC = 3, kH = 224, kW = 224;
constexpr int kHW = kH * kW;          // 50176
constexpr int kS  = 256, kD = 768, kL = 12, kNH = 12, kHD = 64;
constexpr int kMLP = 3072, kNC = 1000;
constexpr int kN  = kS + 1;           // 257 tokens
constexpr int kM  = kB * kN;          // 8224 rows
constexpr int kQKV = 3 * kD;          // 2304

// ---------------------------------------------------------------------------
// Scratch (static device globals -- allowed; runtime allocation is not)
// ---------------------------------------------------------------------------
__device__ float g_x[kM * kD];
__device__ float g_h[kM * kD];
__device__ float g_qkv[kM * kQKV];
__device__ float g_att[kM * kD];
__device__ float g_mlp[kM * kMLP];
__device__ float g_seg[kB * kS * kC];
__device__ float g_cls[kB * kD];

// ---------------------------------------------------------------------------
// Helpers
// ---------------------------------------------------------------------------
__device__ __forceinline__ float gelu_exact(float x) {
    return 0.5f * x * (1.0f + erff(x * 0.70710678118654752440f));
}

__device__ __forceinline__ unsigned packbf(float a, float b) {
    __nv_bfloat162 t = __floats2bfloat162_rn(a, b);
    return *reinterpret_cast<unsigned*>(&t);
}

// bf16 m16n8k16 MMA, fp32 accumulate
__device__ __forceinline__ void mma_bf16(float c[4], const unsigned a[4], const unsigned b[2]) {
    asm volatile(
        "mma.sync.aligned.m16n8k16.row.col.f32.bf16.bf16.f32 "
        "{%0,%1,%2,%3}, {%4,%5,%6,%7}, {%8,%9}, {%0,%1,%2,%3};\n"
        : "+f"(c[0]), "+f"(c[1]), "+f"(c[2]), "+f"(c[3])
        : "r"(a[0]), "r"(a[1]), "r"(a[2]), "r"(a[3]), "r"(b[0]), "r"(b[1]));
}

// ---------------------------------------------------------------------------
// 1) Superpixel segment sums: one block per batch image, smem histogram
// ---------------------------------------------------------------------------
__global__ void seg_sum_kernel(const float* __restrict__ img, const int* __restrict__ seg) {
    __shared__ float sm[kS * kC];
    const int b = blockIdx.x;
    for (int i = threadIdx.x; i < kS * kC; i += blockDim.x) sm[i] = 0.f;
    __syncthreads();
    const int*   sb = seg + (size_t)b * kHW;
    const float* i0 = img + (size_t)(b * kC + 0) * kHW;
    const float* i1 = img + (size_t)(b * kC + 1) * kHW;
    const float* i2 = img + (size_t)(b * kC + 2) * kHW;
    for (int p = threadIdx.x; p < kHW; p += blockDim.x) {
        int s = sb[p];
        atomicAdd(&sm[s * 3 + 0], i0[p]);
        atomicAdd(&sm[s * 3 + 1], i1[p]);
        atomicAdd(&sm[s * 3 + 2], i2[p]);
    }
    __syncthreads();
    for (int i = threadIdx.x; i < kS * kC; i += blockDim.x) g_seg[b * kS * kC + i] = sm[i];
}

// ---------------------------------------------------------------------------
// 2) Build x = concat(cls, seg_mean @ w_fe + b_fe) + pos_embed
// ---------------------------------------------------------------------------
__global__ void embed_kernel(const float* __restrict__ w_fe, const float* __restrict__ b_fe,
                             const float* __restrict__ cls_t, const float* __restrict__ pos) {
    const int tok = blockIdx.x;
    const int b = tok / kN, n = tok % kN;
    float s0 = 0.f, s1 = 0.f, s2 = 0.f;
    if (n > 0) {
        const float* sp = g_seg + (size_t)(b * kS + (n - 1)) * 3;
        const float inv = 1.0f / (float)kHW;
        s0 = sp[0] * inv; s1 = sp[1] * inv; s2 = sp[2] * inv;
    }
    float* xr = g_x + (size_t)tok * kD;
    for (int d = threadIdx.x; d < kD; d += blockDim.x) {
        float pv = pos[n * kD + d];
        float v;
        if (n == 0) v = cls_t[d] + pv;
        else        v = b_fe[d] + pv + s0 * w_fe[d] + s1 * w_fe[kD + d] + s2 * w_fe[2 * kD + d];
        xr[d] = v;
    }
}

// ---------------------------------------------------------------------------
// 3) LayerNorm (one block per row, D=768, 256 threads x 3 elems)
// ---------------------------------------------------------------------------
__global__ __launch_bounds__(256) void ln_kernel(const float* __restrict__ x, float* __restrict__ y,
                          const float* __restrict__ gw, const float* __restrict__ bw,
                          long xstride, long ystride) {
    const int row = blockIdx.x;
    const float* xr = x + (long)row * xstride;
    float*       yr = y + (long)row * ystride;
    const int tid = threadIdx.x;
    float v0 = xr[tid], v1 = xr[tid + 256], v2 = xr[tid + 512];
    __shared__ float red[8];

    float s = v0 + v1 + v2;
    #pragma unroll
    for (int o = 16; o > 0; o >>= 1) s += __shfl_down_sync(0xffffffffu, s, o);
    if ((tid & 31) == 0) red[tid >> 5] = s;
    __syncthreads();
    if (tid < 8) {
        float t = red[tid];
        #pragma unroll
        for (int o = 4; o > 0; o >>= 1) t += __shfl_down_sync(0xffu, t, o);
        if (tid == 0) red[0] = t;
    }
    __syncthreads();
    const float m = red[0] * (1.0f / kD);
    __syncthreads();

    const float d0 = v0 - m, d1 = v1 - m, d2 = v2 - m;
    float q = d0 * d0 + d1 * d1 + d2 * d2;
    #pragma unroll
    for (int o = 16; o > 0; o >>= 1) q += __shfl_down_sync(0xffffffffu, q, o);
    if ((tid & 31) == 0) red[tid >> 5] = q;
    __syncthreads();
    if (tid < 8) {
        float t = red[tid];
        #pragma unroll
        for (int o = 4; o > 0; o >>= 1) t += __shfl_down_sync(0xffu, t, o);
        if (tid == 0) red[0] = t;
    }
    __syncthreads();
    const float inv = rsqrtf(red[0] * (1.0f / kD) + 1e-6f);

    yr[tid]       = d0 * inv * gw[tid]       + bw[tid];
    yr[tid + 256] = d1 * inv * gw[tid + 256] + bw[tid + 256];
    yr[tid + 512] = d2 * inv * gw[tid + 512] + bw[tid + 512];
}

// ---------------------------------------------------------------------------
// 4) Split-bf16 GEMM: C = epilogue(A[M,K] @ W[K,N] + bias [, +res | gelu])
//    BM=BN=128, BK=32, 256 threads, warp tile 32x64, m16n8k16.bf16 hi/lo split
//    (ah*bh + al*bh + ah*bl => ~16-bit mantissa accuracy, fp32 accumulate)
//    Double-buffered smem + register prefetch of next tile.
//
//    smem (uint32 units) per buffer:
//      Ah[128][20] (16 used per row: K-pairs)   2560
//      Al[128][20]                              2560
//      Bh[16][136] (row q = K-pair, col n)      2176
//      Bl[16][136]                              2176
//    buffer stride 9472 u32; two buffers = 75,776 bytes.
// ---------------------------------------------------------------------------
constexpr int BUF_U32   = 9472;
constexpr int GEMM_SMEM = 2 * BUF_U32 * 4;   // 75776 B

template <int OP>   // 0: +bias   1: +bias, gelu   2: +bias, +res
__global__ __launch_bounds__(256) void gemm_kernel(
    const float* __restrict__ A, const float* __restrict__ Wm,
    const float* __restrict__ bias, const float* __restrict__ res,
    float* __restrict__ Cout, int M, int N, int K)
{
    extern __shared__ unsigned smemu[];

    const int tid = threadIdx.x;
    const int wid = tid >> 5, lane = tid & 31;
    const int gp = lane >> 2, tg = lane & 3;
    const int wm = (wid >> 1) * 32;     // 4 warps along M
    const int wn = (wid & 1) * 64;      // 2 warps along N
    const int m0 = blockIdx.y * 128;
    const int n0 = blockIdx.x * 128;

    float c[2][8][4];
    #pragma unroll
    for (int i = 0; i < 2; i++)
        #pragma unroll
        for (int j = 0; j < 8; j++)
            #pragma unroll
            for (int r = 0; r < 4; r++) c[i][j][r] = 0.f;

    // loader indices
    const int arow = tid >> 3, ac4 = tid & 7;      // A: 4 rows-of-32, float4 col
    const int bq   = tid >> 5, bc4 = tid & 31;     // B: 2 q-groups of 8, float4 col

    float4 apf[4];
    float4 bpf[2][2];

    const int nK = K >> 5;

    auto prefetch = [&](int k0) {
        #pragma unroll
        for (int p = 0; p < 4; p++) {
            const int grow = m0 + p * 32 + arow;
            if (grow < M) apf[p] = *(const float4*)(A + (size_t)grow * K + k0 + ac4 * 4);
            else          apf[p] = make_float4(0.f, 0.f, 0.f, 0.f);
        }
        #pragma unroll
        for (int p = 0; p < 2; p++) {
            const int q = p * 8 + bq;
            const float* bp = Wm + (size_t)(k0 + 2 * q) * N + n0 + bc4 * 4;
            bpf[p][0] = *(const float4*)bp;
            bpf[p][1] = *(const float4*)(bp + N);
        }
    };

    auto store_buf = [&](int buf) {
        unsigned* Ah = smemu + buf * BUF_U32;
        unsigned* Al = Ah + 2560;
        unsigned* Bh = Ah + 5120;
        unsigned* Bl = Ah + 7296;
        #pragma unroll
        for (int p = 0; p < 4; p++) {
            const int r = p * 32 + arow;
            float v[4] = {apf[p].x, apf[p].y, apf[p].z, apf[p].w};
            float hf[4], lf[4];
            #pragma unroll
            for (int i = 0; i < 4; i++) {
                hf[i] = __bfloat162float(__float2bfloat16(v[i]));
                lf[i] = v[i] - hf[i];
            }
            Ah[r * 20 + ac4 * 2]     = packbf(hf[0], hf[1]);
            Ah[r * 20 + ac4 * 2 + 1] = packbf(hf[2], hf[3]);
            Al[r * 20 + ac4 * 2]     = packbf(lf[0], lf[1]);
            Al[r * 20 + ac4 * 2 + 1] = packbf(lf[2], lf[3]);
        }
        #pragma unroll
        for (int p = 0; p < 2; p++) {
            const int q = p * 8 + bq;
            float v0[4] = {bpf[p][0].x, bpf[p][0].y, bpf[p][0].z, bpf[p][0].w};
            float v1[4] = {bpf[p][1].x, bpf[p][1].y, bpf[p][1].z, bpf[p][1].w};
            #pragma unroll
            for (int i = 0; i < 4; i++) {
                float h0 = __bfloat162float(__float2bfloat16(v0[i]));
                float h1 = __bfloat162float(__float2bfloat16(v1[i]));
                Bh[q * 136 + bc4 * 4 + i] = packbf(h0, h1);
                Bl[q * 136 + bc4 * 4 + i] = packbf(v0[i] - h0, v1[i] - h1);
            }
        }
    };

    prefetch(0);
    store_buf(0);
    __syncthreads();

    for (int kt = 0; kt < nK; kt++) {
        if (kt + 1 < nK) prefetch((kt + 1) << 5);

        const unsigned* Ah = smemu + (kt & 1) * BUF_U32;
        const unsigned* Al = Ah + 2560;
        const unsigned* Bh = Ah + 5120;
        const unsigned* Bl = Ah + 7296;

        #pragma unroll
        for (int kk = 0; kk < 2; kk++) {
            unsigned ah[2][4], al[2][4], bb[8][2];
            const int kc = kk * 8 + tg;
            #pragma unroll
            for (int mi = 0; mi < 2; mi++) {
                const int rb = wm + mi * 16 + gp;
                ah[mi][0] = Ah[rb * 20 + kc];
                ah[mi][1] = Ah[(rb + 8) * 20 + kc];
                ah[mi][2] = Ah[rb * 20 + kc + 4];
                ah[mi][3] = Ah[(rb + 8) * 20 + kc + 4];
                al[mi][0] = Al[rb * 20 + kc];
                al[mi][1] = Al[(rb + 8) * 20 + kc];
                al[mi][2] = Al[rb * 20 + kc + 4];
                al[mi][3] = Al[(rb + 8) * 20 + kc + 4];
            }
            #pragma unroll
            for (int ni = 0; ni < 8; ni++) {
                const int col = wn + ni * 8 + gp;
                bb[ni][0] = Bh[(kk * 8 + tg) * 136 + col];
                bb[ni][1] = Bh[(kk * 8 + 4 + tg) * 136 + col];
            }
            #pragma unroll
            for (int mi = 0; mi < 2; mi++)
                #pragma unroll
                for (int ni = 0; ni < 8; ni++) {
                    mma_bf16(c[mi][ni], ah[mi], bb[ni]);   // hi*hi
                    mma_bf16(c[mi][ni], al[mi], bb[ni]);   // lo*hi
                }
            #pragma unroll
            for (int ni = 0; ni < 8; ni++) {
                const int col = wn + ni * 8 + gp;
                bb[ni][0] = Bl[(kk * 8 + tg) * 136 + col];
                bb[ni][1] = Bl[(kk * 8 + 4 + tg) * 136 + col];
            }
            #pragma unroll
            for (int mi = 0; mi < 2; mi++)
                #pragma unroll
                for (int ni = 0; ni < 8; ni++)
                    mma_bf16(c[mi][ni], ah[mi], bb[ni]);   // hi*lo
        }

        if (kt + 1 < nK) store_buf((kt + 1) & 1);
        __syncthreads();
    }

    #pragma unroll
    for (int mi = 0; mi < 2; mi++)
        #pragma unroll
        for (int ni = 0; ni < 8; ni++) {
            const int col = n0 + wn + ni * 8 + tg * 2;
            const float b0 = bias[col], b1 = bias[col + 1];
            #pragma unroll
            for (int hh = 0; hh < 2; hh++) {
                const int row = m0 + wm + mi * 16 + gp + hh * 8;
                if (row < M) {
                    float v0 = c[mi][ni][hh * 2 + 0] + b0;
                    float v1 = c[mi][ni][hh * 2 + 1] + b1;
                    if (OP == 1) { v0 = gelu_exact(v0); v1 = gelu_exact(v1); }
                    if (OP == 2) {
                        float2 rr = *(const float2*)(res + (size_t)row * N + col);
                        v0 += rr.x; v1 += rr.y;
                    }
                    *(float2*)(Cout + (size_t)row * N + col) = make_float2(v0, v1);
                }
            }
        }
}

// ---------------------------------------------------------------------------
// 5) Fused attention: one block per (b, head). K,V in smem; softmax per row.
// ---------------------------------------------------------------------------
constexpr int ATTN_SMEM = (2 * 257 * 65 + 8 * 64) * 4;  // 135688 B

__global__ __launch_bounds__(256) void attn_kernel() {
    extern __shared__ float sm[];
    float* Ks = sm;                     // [257][65]
    float* Vs = sm + 257 * 65;          // [257][65]
    float* qs = sm + 2 * 257 * 65;      // [8][64]

    const int b = blockIdx.x / kNH, hh = blockIdx.x % kNH;
    const int tid = threadIdx.x, w = tid >> 5, lane = tid & 31;
    const float* base = g_qkv + (size_t)b * kN * kQKV + hh * kHD;

    for (int i = tid; i < kN * kHD; i += 256) {
        const int n = i >> 6, d = i & 63;
        Ks[n * 65 + d] = base[(size_t)n * kQKV + kD + d];
        Vs[n * 65 + d] = base[(size_t)n * kQKV + 2 * kD + d];
    }
    __syncthreads();

    for (int r = w; r < kN; r += 8) {
        qs[w * 64 + lane]      = base[(size_t)r * kQKV + lane];
        qs[w * 64 + lane + 32] = base[(size_t)r * kQKV + lane + 32];
        __syncwarp();
        float q[64];
        #pragma unroll
        for (int k = 0; k < 64; k++) q[k] = qs[w * 64 + k];
        __syncwarp();

        float sc[9];
        #pragma unroll
        for (int t = 0; t < 9; t++) {
            const int j = t * 32 + lane;
            const int jj = (j < kN) ? j : 0;
            float acc = 0.f;
            #pragma unroll
            for (int k = 0; k < 64; k++) acc += q[k] * Ks[jj * 65 + k];
            sc[t] = (j < kN) ? acc * 0.125f : -__int_as_float(0x7f800000);
        }
        float mx = sc[0];
        #pragma unroll
        for (int t = 1; t < 9; t++) mx = fmaxf(mx, sc[t]);
        #pragma unroll
        for (int o = 16; o > 0; o >>= 1) mx = fmaxf(mx, __shfl_xor_sync(0xffffffffu, mx, o));
        float sum = 0.f;
        #pragma unroll
        for (int t = 0; t < 9; t++) { sc[t] = expf(sc[t] - mx); sum += sc[t]; }
        #pragma unroll
        for (int o = 16; o > 0; o >>= 1) sum += __shfl_xor_sync(0xffffffffu, sum, o);
        const float inv = 1.0f / sum;
        #pragma unroll
        for (int t = 0; t < 9; t++) sc[t] *= inv;

        float a0 = 0.f, a1 = 0.f;
        #pragma unroll
        for (int t = 0; t < 9; t++) {
            const int lim = (t == 8) ? 1 : 32;
            #pragma unroll
            for (int s2 = 0; s2 < 32; s2++) {
                if (s2 >= lim) break;
                const float pv = __shfl_sync(0xffffffffu, sc[t], s2);
                const int j = t * 32 + s2;
                a0 += pv * Vs[j * 65 + lane];
                a1 += pv * Vs[j * 65 + 32 + lane];
            }
        }
        float* orow = g_att + (size_t)(b * kN + r) * kD + hh * kHD;
        orow[lane]      = a0;
        orow[lane + 32] = a1;
    }
}

// ---------------------------------------------------------------------------
// 6) Head: out[b, c] = cls_ln[b] . head_w[:, c] + head_b[c]
// ---------------------------------------------------------------------------
__global__ void head_kernel(const float* __restrict__ hw, const float* __restrict__ hb,
                            float* __restrict__ out) {
    __shared__ float xs[kD];
    const int b = blockIdx.y;
    const int col = blockIdx.x * 256 + threadIdx.x;
    for (int i = threadIdx.x; i < kD; i += 256) xs[i] = g_cls[b * kD + i];
    __syncthreads();
    if (col < kNC) {
        float acc = hb[col];
        #pragma unroll 4
        for (int k = 0; k < kD; k++) acc += xs[k] * hw[(size_t)k * kNC + col];
        out[(size_t)b * kNC + col] = acc;
    }
}

// ---------------------------------------------------------------------------
// Launch
// ---------------------------------------------------------------------------
extern "C" void kernel_launch(void* const* d_in, const int* in_sizes, int n_in,
                              void* d_out, int out_size) {
    const float* img    = (const float*)d_in[0];
    const int*   seg    = (const int*)  d_in[1];
    const float* w_fe   = (const float*)d_in[2];
    const float* b_fe   = (const float*)d_in[3];
    const float* cls_t  = (const float*)d_in[4];
    const float* pos    = (const float*)d_in[5];
    const float* ln1_g  = (const float*)d_in[6];
    const float* ln1_b  = (const float*)d_in[7];
    const float* qkv_w  = (const float*)d_in[8];
    const float* qkv_b  = (const float*)d_in[9];
    const float* proj_w = (const float*)d_in[10];
    const float* proj_b = (const float*)d_in[11];
    const float* ln2_g  = (const float*)d_in[12];
    const float* ln2_b  = (const float*)d_in[13];
    const float* mlp_w1 = (const float*)d_in[14];
    const float* mlp_b1 = (const float*)d_in[15];
    const float* mlp_w2 = (const float*)d_in[16];
    const float* mlp_b2 = (const float*)d_in[17];
    const float* norm_g = (const float*)d_in[18];
    const float* norm_b = (const float*)d_in[19];
    const float* head_w = (const float*)d_in[20];
    const float* head_b = (const float*)d_in[21];

    cudaFuncSetAttribute(attn_kernel,    cudaFuncAttributeMaxDynamicSharedMemorySize, ATTN_SMEM);
    cudaFuncSetAttribute(gemm_kernel<0>, cudaFuncAttributeMaxDynamicSharedMemorySize, GEMM_SMEM);
    cudaFuncSetAttribute(gemm_kernel<1>, cudaFuncAttributeMaxDynamicSharedMemorySize, GEMM_SMEM);
    cudaFuncSetAttribute(gemm_kernel<2>, cudaFuncAttributeMaxDynamicSharedMemorySize, GEMM_SMEM);

    float *px, *ph, *pq, *pa, *pm, *pc;
    cudaGetSymbolAddress((void**)&px, g_x);
    cudaGetSymbolAddress((void**)&ph, g_h);
    cudaGetSymbolAddress((void**)&pq, g_qkv);
    cudaGetSymbolAddress((void**)&pa, g_att);
    cudaGetSymbolAddress((void**)&pm, g_mlp);
    cudaGetSymbolAddress((void**)&pc, g_cls);

    seg_sum_kernel<<<kB, 256>>>(img, seg);
    embed_kernel<<<kM, 256>>>(w_fe, b_fe, cls_t, pos);

    const dim3 gQKV(kQKV / 128, (kM + 127) / 128);
    const dim3 gD  (kD   / 128, (kM + 127) / 128);
    const dim3 gMLP(kMLP / 128, (kM + 127) / 128);

    for (int l = 0; l < kL; l++) {
        ln_kernel<<<kM, 256>>>(px, ph, ln1_g + (size_t)l * kD, ln1_b + (size_t)l * kD, kD, kD);
        gemm_kernel<0><<<gQKV, 256, GEMM_SMEM>>>(ph, qkv_w + (size_t)l * kD * kQKV,
                                                 qkv_b + (size_t)l * kQKV, nullptr, pq,
                                                 kM, kQKV, kD);
        attn_kernel<<<kB * kNH, 256, ATTN_SMEM>>>();
        gemm_kernel<2><<<gD, 256, GEMM_SMEM>>>(pa, proj_w + (size_t)l * kD * kD,
                                               proj_b + (size_t)l * kD, px, px,
                                               kM, kD, kD);
        ln_kernel<<<kM, 256>>>(px, ph, ln2_g + (size_t)l * kD, ln2_b + (size_t)l * kD, kD, kD);
        gemm_kernel<1><<<gMLP, 256, GEMM_SMEM>>>(ph, mlp_w1 + (size_t)l * kD * kMLP,
                                                 mlp_b1 + (size_t)l * kMLP, nullptr, pm,
                                                 kM, kMLP, kD);
        gemm_kernel<2><<<gD, 256, GEMM_SMEM>>>(pm, mlp_w2 + (size_t)l * kMLP * kD,
                                               mlp_b2 + (size_t)l * kD, px, px,
                                               kM, kD, kMLP);
    }

    // Final LN on cls rows only (row b lives at x + b*257*768), then head.
    ln_kernel<<<kB, 256>>>(px, pc, norm_g, norm_b, (long)kN * kD, (long)kD);
    head_kernel<<<dim3((kNC + 255) / 256, kB), 256>>>(head_w, head_b, (float*)d_out);
}

// round 7
// speedup vs baseline: 1.7239x; 1.1807x over previous
#include <cuda_runtime.h>
#include <cuda_bf16.h>
#include <math.h>

// ---------------------------------------------------------------------------
// Problem constants
// ---------------------------------------------------------------------------
constexpr int kB  = 32, kC = 3, kH = 224, kW = 224;
constexpr int kHW = kH * kW;          // 50176
constexpr int kS  = 256, kD = 768, kL = 12, kNH = 12, kHD = 64;
constexpr int kMLP = 3072, kNC = 1000;
constexpr int kN  = kS + 1;           // 257 tokens
constexpr int kM  = kB * kN;          // 8224 rows
constexpr int kQKV = 3 * kD;          // 2304

// ---------------------------------------------------------------------------
// Scratch (static device globals -- allowed; runtime allocation is not)
// ---------------------------------------------------------------------------
__device__ float g_x[kM * kD];
__device__ float g_h[kM * kD];
__device__ float g_qkv[kM * kQKV];
__device__ float g_att[kM * kD];
__device__ float g_mlp[kM * kMLP];
__device__ float g_seg[kB * kS * kC];
__device__ float g_cls[kB * kD];

// ---------------------------------------------------------------------------
// Helpers
// ---------------------------------------------------------------------------
__device__ __forceinline__ float gelu_exact(float x) {
    return 0.5f * x * (1.0f + erff(x * 0.70710678118654752440f));
}

__device__ __forceinline__ unsigned packbf(float a, float b) {
    __nv_bfloat162 t = __floats2bfloat162_rn(a, b);
    return *reinterpret_cast<unsigned*>(&t);
}

// bf16 m16n8k16 MMA, fp32 accumulate
__device__ __forceinline__ void mma_bf16(float c[4], const unsigned a[4], const unsigned b[2]) {
    asm volatile(
        "mma.sync.aligned.m16n8k16.row.col.f32.bf16.bf16.f32 "
        "{%0,%1,%2,%3}, {%4,%5,%6,%7}, {%8,%9}, {%0,%1,%2,%3};\n"
        : "+f"(c[0]), "+f"(c[1]), "+f"(c[2]), "+f"(c[3])
        : "r"(a[0]), "r"(a[1]), "r"(a[2]), "r"(a[3]), "r"(b[0]), "r"(b[1]));
}

// ---------------------------------------------------------------------------
// 1) Superpixel segment sums: one block per batch image, smem histogram
// ---------------------------------------------------------------------------
__global__ void seg_sum_kernel(const float* __restrict__ img, const int* __restrict__ seg) {
    __shared__ float sm[kS * kC];
    const int b = blockIdx.x;
    for (int i = threadIdx.x; i < kS * kC; i += blockDim.x) sm[i] = 0.f;
    __syncthreads();
    const int*   sb = seg + (size_t)b * kHW;
    const float* i0 = img + (size_t)(b * kC + 0) * kHW;
    const float* i1 = img + (size_t)(b * kC + 1) * kHW;
    const float* i2 = img + (size_t)(b * kC + 2) * kHW;
    for (int p = threadIdx.x; p < kHW; p += blockDim.x) {
        int s = sb[p];
        atomicAdd(&sm[s * 3 + 0], i0[p]);
        atomicAdd(&sm[s * 3 + 1], i1[p]);
        atomicAdd(&sm[s * 3 + 2], i2[p]);
    }
    __syncthreads();
    for (int i = threadIdx.x; i < kS * kC; i += blockDim.x) g_seg[b * kS * kC + i] = sm[i];
}

// ---------------------------------------------------------------------------
// 2) Build x = concat(cls, seg_mean @ w_fe + b_fe) + pos_embed
// ---------------------------------------------------------------------------
__global__ void embed_kernel(const float* __restrict__ w_fe, const float* __restrict__ b_fe,
                             const float* __restrict__ cls_t, const float* __restrict__ pos) {
    const int tok = blockIdx.x;
    const int b = tok / kN, n = tok % kN;
    float s0 = 0.f, s1 = 0.f, s2 = 0.f;
    if (n > 0) {
        const float* sp = g_seg + (size_t)(b * kS + (n - 1)) * 3;
        const float inv = 1.0f / (float)kHW;
        s0 = sp[0] * inv; s1 = sp[1] * inv; s2 = sp[2] * inv;
    }
    float* xr = g_x + (size_t)tok * kD;
    for (int d = threadIdx.x; d < kD; d += blockDim.x) {
        float pv = pos[n * kD + d];
        float v;
        if (n == 0) v = cls_t[d] + pv;
        else        v = b_fe[d] + pv + s0 * w_fe[d] + s1 * w_fe[kD + d] + s2 * w_fe[2 * kD + d];
        xr[d] = v;
    }
}

// ---------------------------------------------------------------------------
// 3) LayerNorm (one block per row, D=768, 256 threads x 3 elems)
// ---------------------------------------------------------------------------
__global__ __launch_bounds__(256) void ln_kernel(const float* __restrict__ x, float* __restrict__ y,
                          const float* __restrict__ gw, const float* __restrict__ bw,
                          long xstride, long ystride) {
    const int row = blockIdx.x;
    const float* xr = x + (long)row * xstride;
    float*       yr = y + (long)row * ystride;
    const int tid = threadIdx.x;
    float v0 = xr[tid], v1 = xr[tid + 256], v2 = xr[tid + 512];
    __shared__ float red[8];

    float s = v0 + v1 + v2;
    #pragma unroll
    for (int o = 16; o > 0; o >>= 1) s += __shfl_down_sync(0xffffffffu, s, o);
    if ((tid & 31) == 0) red[tid >> 5] = s;
    __syncthreads();
    if (tid < 8) {
        float t = red[tid];
        #pragma unroll
        for (int o = 4; o > 0; o >>= 1) t += __shfl_down_sync(0xffu, t, o);
        if (tid == 0) red[0] = t;
    }
    __syncthreads();
    const float m = red[0] * (1.0f / kD);
    __syncthreads();

    const float d0 = v0 - m, d1 = v1 - m, d2 = v2 - m;
    float q = d0 * d0 + d1 * d1 + d2 * d2;
    #pragma unroll
    for (int o = 16; o > 0; o >>= 1) q += __shfl_down_sync(0xffffffffu, q, o);
    if ((tid & 31) == 0) red[tid >> 5] = q;
    __syncthreads();
    if (tid < 8) {
        float t = red[tid];
        #pragma unroll
        for (int o = 4; o > 0; o >>= 1) t += __shfl_down_sync(0xffu, t, o);
        if (tid == 0) red[0] = t;
    }
    __syncthreads();
    const float inv = rsqrtf(red[0] * (1.0f / kD) + 1e-6f);

    yr[tid]       = d0 * inv * gw[tid]       + bw[tid];
    yr[tid + 256] = d1 * inv * gw[tid + 256] + bw[tid + 256];
    yr[tid + 512] = d2 * inv * gw[tid + 512] + bw[tid + 512];
}

// ---------------------------------------------------------------------------
// 4) Split-bf16 GEMM: C = epilogue(A[M,K] @ W[K,N] + bias [, +res | gelu])
//    BM=BN=128, BK=32, 256 threads, warp tile 32x64, m16n8k16.bf16 hi/lo split
//    Double-buffered smem + register prefetch. 2 CTAs/SM via launch bounds.
// ---------------------------------------------------------------------------
constexpr int BUF_U32   = 9472;
constexpr int GEMM_SMEM = 2 * BUF_U32 * 4;   // 75776 B

template <int OP>   // 0: +bias   1: +bias, gelu   2: +bias, +res
__global__ __launch_bounds__(256, 2) void gemm_kernel(
    const float* __restrict__ A, const float* __restrict__ Wm,
    const float* __restrict__ bias, const float* __restrict__ res,
    float* __restrict__ Cout, int M, int N, int K)
{
    extern __shared__ unsigned smemu[];

    const int tid = threadIdx.x;
    const int wid = tid >> 5, lane = tid & 31;
    const int gp = lane >> 2, tg = lane & 3;
    const int wm = (wid >> 1) * 32;     // 4 warps along M
    const int wn = (wid & 1) * 64;      // 2 warps along N
    const int m0 = blockIdx.y * 128;
    const int n0 = blockIdx.x * 128;

    float c[2][8][4];
    #pragma unroll
    for (int i = 0; i < 2; i++)
        #pragma unroll
        for (int j = 0; j < 8; j++)
            #pragma unroll
            for (int r = 0; r < 4; r++) c[i][j][r] = 0.f;

    // loader indices
    const int arow = tid >> 3, ac4 = tid & 7;      // A: 4 rows-of-32, float4 col
    const int bq   = tid >> 5, bc4 = tid & 31;     // B: 2 q-groups of 8, float4 col

    float4 apf[4];
    float4 bpf[2][2];

    const int nK = K >> 5;

    auto prefetch = [&](int k0) {
        #pragma unroll
        for (int p = 0; p < 4; p++) {
            const int grow = m0 + p * 32 + arow;
            if (grow < M) apf[p] = *(const float4*)(A + (size_t)grow * K + k0 + ac4 * 4);
            else          apf[p] = make_float4(0.f, 0.f, 0.f, 0.f);
        }
        #pragma unroll
        for (int p = 0; p < 2; p++) {
            const int q = p * 8 + bq;
            const float* bp = Wm + (size_t)(k0 + 2 * q) * N + n0 + bc4 * 4;
            bpf[p][0] = *(const float4*)bp;
            bpf[p][1] = *(const float4*)(bp + N);
        }
    };

    auto store_buf = [&](int buf) {
        unsigned* Ah = smemu + buf * BUF_U32;
        unsigned* Al = Ah + 2560;
        unsigned* Bh = Ah + 5120;
        unsigned* Bl = Ah + 7296;
        #pragma unroll
        for (int p = 0; p < 4; p++) {
            const int r = p * 32 + arow;
            float v[4] = {apf[p].x, apf[p].y, apf[p].z, apf[p].w};
            float hf[4], lf[4];
            #pragma unroll
            for (int i = 0; i < 4; i++) {
                hf[i] = __bfloat162float(__float2bfloat16(v[i]));
                lf[i] = v[i] - hf[i];
            }
            Ah[r * 20 + ac4 * 2]     = packbf(hf[0], hf[1]);
            Ah[r * 20 + ac4 * 2 + 1] = packbf(hf[2], hf[3]);
            Al[r * 20 + ac4 * 2]     = packbf(lf[0], lf[1]);
            Al[r * 20 + ac4 * 2 + 1] = packbf(lf[2], lf[3]);
        }
        #pragma unroll
        for (int p = 0; p < 2; p++) {
            const int q = p * 8 + bq;
            float v0[4] = {bpf[p][0].x, bpf[p][0].y, bpf[p][0].z, bpf[p][0].w};
            float v1[4] = {bpf[p][1].x, bpf[p][1].y, bpf[p][1].z, bpf[p][1].w};
            #pragma unroll
            for (int i = 0; i < 4; i++) {
                float h0 = __bfloat162float(__float2bfloat16(v0[i]));
                float h1 = __bfloat162float(__float2bfloat16(v1[i]));
                Bh[q * 136 + bc4 * 4 + i] = packbf(h0, h1);
                Bl[q * 136 + bc4 * 4 + i] = packbf(v0[i] - h0, v1[i] - h1);
            }
        }
    };

    prefetch(0);
    store_buf(0);
    __syncthreads();

    for (int kt = 0; kt < nK; kt++) {
        if (kt + 1 < nK) prefetch((kt + 1) << 5);

        const unsigned* Ah = smemu + (kt & 1) * BUF_U32;
        const unsigned* Al = Ah + 2560;
        const unsigned* Bh = Ah + 5120;
        const unsigned* Bl = Ah + 7296;

        #pragma unroll
        for (int kk = 0; kk < 2; kk++) {
            unsigned ah[2][4], al[2][4], bb[8][2];
            const int kc = kk * 8 + tg;
            #pragma unroll
            for (int mi = 0; mi < 2; mi++) {
                const int rb = wm + mi * 16 + gp;
                ah[mi][0] = Ah[rb * 20 + kc];
                ah[mi][1] = Ah[(rb + 8) * 20 + kc];
                ah[mi][2] = Ah[rb * 20 + kc + 4];
                ah[mi][3] = Ah[(rb + 8) * 20 + kc + 4];
                al[mi][0] = Al[rb * 20 + kc];
                al[mi][1] = Al[(rb + 8) * 20 + kc];
                al[mi][2] = Al[rb * 20 + kc + 4];
                al[mi][3] = Al[(rb + 8) * 20 + kc + 4];
            }
            #pragma unroll
            for (int ni = 0; ni < 8; ni++) {
                const int col = wn + ni * 8 + gp;
                bb[ni][0] = Bh[(kk * 8 + tg) * 136 + col];
                bb[ni][1] = Bh[(kk * 8 + 4 + tg) * 136 + col];
            }
            #pragma unroll
            for (int mi = 0; mi < 2; mi++)
                #pragma unroll
                for (int ni = 0; ni < 8; ni++) {
                    mma_bf16(c[mi][ni], ah[mi], bb[ni]);   // hi*hi
                    mma_bf16(c[mi][ni], al[mi], bb[ni]);   // lo*hi
                }
            #pragma unroll
            for (int ni = 0; ni < 8; ni++) {
                const int col = wn + ni * 8 + gp;
                bb[ni][0] = Bl[(kk * 8 + tg) * 136 + col];
                bb[ni][1] = Bl[(kk * 8 + 4 + tg) * 136 + col];
            }
            #pragma unroll
            for (int mi = 0; mi < 2; mi++)
                #pragma unroll
                for (int ni = 0; ni < 8; ni++)
                    mma_bf16(c[mi][ni], ah[mi], bb[ni]);   // hi*lo
        }

        if (kt + 1 < nK) store_buf((kt + 1) & 1);
        __syncthreads();
    }

    #pragma unroll
    for (int mi = 0; mi < 2; mi++)
        #pragma unroll
        for (int ni = 0; ni < 8; ni++) {
            const int col = n0 + wn + ni * 8 + tg * 2;
            const float b0 = bias[col], b1 = bias[col + 1];
            #pragma unroll
            for (int hh = 0; hh < 2; hh++) {
                const int row = m0 + wm + mi * 16 + gp + hh * 8;
                if (row < M) {
                    float v0 = c[mi][ni][hh * 2 + 0] + b0;
                    float v1 = c[mi][ni][hh * 2 + 1] + b1;
                    if (OP == 1) { v0 = gelu_exact(v0); v1 = gelu_exact(v1); }
                    if (OP == 2) {
                        float2 rr = *(const float2*)(res + (size_t)row * N + col);
                        v0 += rr.x; v1 += rr.y;
                    }
                    *(float2*)(Cout + (size_t)row * N + col) = make_float2(v0, v1);
                }
            }
        }
}

// ---------------------------------------------------------------------------
// 5) Fused attention, 4-row register blocking per warp.
//    Each warp handles 4 rows per pass; Q staged as float4[k][4r], probs as
//    float4[j][4r] so one LDS.128 broadcast feeds 4 (QK) / 8 (AV) FMAs.
//    smem floats: Ks[0,16705) pad->16720 | Vs[16720,+16705) pad->33440 |
//                 Q4[33440, +8*256) | P4[35488, +8*1152) -> 44704 floats.
// ---------------------------------------------------------------------------
constexpr int ATTN_SMEM = 44704 * 4;   // 178816 B

__global__ __launch_bounds__(256) void attn_kernel() {
    extern __shared__ float sm[];
    float* Ks = sm;                      // [257][65]
    float* Vs = sm + 16720;              // [257][65]
    float* Q4 = sm + 33440;              // [8 warps][64 k][4 rows]
    float* P4 = sm + 35488;              // [8 warps][288 j][4 rows]

    const int b = blockIdx.x / kNH, hh = blockIdx.x % kNH;
    const int tid = threadIdx.x, w = tid >> 5, lane = tid & 31;
    const float* base = g_qkv + (size_t)b * kN * kQKV + hh * kHD;

    for (int i = tid; i < kN * kHD; i += 256) {
        const int n = i >> 6, d = i & 63;
        Ks[n * 65 + d] = base[(size_t)n * kQKV + kD + d];
        Vs[n * 65 + d] = base[(size_t)n * kQKV + 2 * kD + d];
    }
    __syncthreads();

    float* Q4w = Q4 + w * 256;
    float* P4w = P4 + w * 1152;

    for (int pass = 0; pass < 9; pass++) {
        const int r0 = pass * 32 + w * 4;

        // stage Q for 4 rows (clamped; extra rows never stored)
        #pragma unroll
        for (int hk = 0; hk < 2; hk++) {
            const int k = hk * 32 + lane;
            #pragma unroll
            for (int rr = 0; rr < 4; rr++) {
                int r = r0 + rr; if (r >= kN) r = kN - 1;
                Q4w[k * 4 + rr] = base[(size_t)r * kQKV + k];
            }
        }
        __syncwarp();

        // scores: lane owns j = t*32+lane, 4 rows at once
        float s[4][9];
        #pragma unroll
        for (int t = 0; t < 9; t++) {
            const int j = t * 32 + lane;
            const int jj = (j < kN) ? j : 0;
            const float* kr = Ks + jj * 65;
            float a0 = 0.f, a1 = 0.f, a2 = 0.f, a3 = 0.f;
            #pragma unroll 16
            for (int k = 0; k < 64; k++) {
                const float kv = kr[k];
                const float4 qv = *(const float4*)(Q4w + k * 4);
                a0 += qv.x * kv; a1 += qv.y * kv;
                a2 += qv.z * kv; a3 += qv.w * kv;
            }
            const float ninf = -__int_as_float(0x7f800000);
            s[0][t] = (j < kN) ? a0 * 0.125f : ninf;
            s[1][t] = (j < kN) ? a1 * 0.125f : ninf;
            s[2][t] = (j < kN) ? a2 * 0.125f : ninf;
            s[3][t] = (j < kN) ? a3 * 0.125f : ninf;
        }

        // softmax per row; write probs as float4-per-j
        #pragma unroll
        for (int rr = 0; rr < 4; rr++) {
            float mx = s[rr][0];
            #pragma unroll
            for (int t = 1; t < 9; t++) mx = fmaxf(mx, s[rr][t]);
            #pragma unroll
            for (int o = 16; o > 0; o >>= 1) mx = fmaxf(mx, __shfl_xor_sync(0xffffffffu, mx, o));
            float sum = 0.f;
            #pragma unroll
            for (int t = 0; t < 9; t++) { s[rr][t] = __expf(s[rr][t] - mx); sum += s[rr][t]; }
            #pragma unroll
            for (int o = 16; o > 0; o >>= 1) sum += __shfl_xor_sync(0xffffffffu, sum, o);
            const float inv = 1.0f / sum;
            #pragma unroll
            for (int t = 0; t < 9; t++) P4w[(t * 32 + lane) * 4 + rr] = s[rr][t] * inv;
        }
        __syncwarp();

        // AV: lane owns dims (lane, lane+32); 4 rows at once
        float o0[4] = {0.f, 0.f, 0.f, 0.f};
        float o1[4] = {0.f, 0.f, 0.f, 0.f};
        #pragma unroll 4
        for (int j = 0; j < kN; j++) {
            const float v0 = Vs[j * 65 + lane];
            const float v1 = Vs[j * 65 + 32 + lane];
            const float4 p = *(const float4*)(P4w + j * 4);
            o0[0] += p.x * v0; o1[0] += p.x * v1;
            o0[1] += p.y * v0; o1[1] += p.y * v1;
            o0[2] += p.z * v0; o1[2] += p.z * v1;
            o0[3] += p.w * v0; o1[3] += p.w * v1;
        }

        #pragma unroll
        for (int rr = 0; rr < 4; rr++) {
            const int r = r0 + rr;
            if (r < kN) {
                float* orow = g_att + (size_t)(b * kN + r) * kD + hh * kHD;
                orow[lane]      = o0[rr];
                orow[lane + 32] = o1[rr];
            }
        }
        __syncwarp();
    }
}

// ---------------------------------------------------------------------------
// 6) Head: out[b, c] = cls_ln[b] . head_w[:, c] + head_b[c]
// ---------------------------------------------------------------------------
__global__ void head_kernel(const float* __restrict__ hw, const float* __restrict__ hb,
                            float* __restrict__ out) {
    __shared__ float xs[kD];
    const int b = blockIdx.y;
    const int col = blockIdx.x * 256 + threadIdx.x;
    for (int i = threadIdx.x; i < kD; i += 256) xs[i] = g_cls[b * kD + i];
    __syncthreads();
    if (col < kNC) {
        float acc = hb[col];
        #pragma unroll 4
        for (int k = 0; k < kD; k++) acc += xs[k] * hw[(size_t)k * kNC + col];
        out[(size_t)b * kNC + col] = acc;
    }
}

// ---------------------------------------------------------------------------
// Launch
// ---------------------------------------------------------------------------
extern "C" void kernel_launch(void* const* d_in, const int* in_sizes, int n_in,
                              void* d_out, int out_size) {
    const float* img    = (const float*)d_in[0];
    const int*   seg    = (const int*)  d_in[1];
    const float* w_fe   = (const float*)d_in[2];
    const float* b_fe   = (const float*)d_in[3];
    const float* cls_t  = (const float*)d_in[4];
    const float* pos    = (const float*)d_in[5];
    const float* ln1_g  = (const float*)d_in[6];
    const float* ln1_b  = (const float*)d_in[7];
    const float* qkv_w  = (const float*)d_in[8];
    const float* qkv_b  = (const float*)d_in[9];
    const float* proj_w = (const float*)d_in[10];
    const float* proj_b = (const float*)d_in[11];
    const float* ln2_g  = (const float*)d_in[12];
    const float* ln2_b  = (const float*)d_in[13];
    const float* mlp_w1 = (const float*)d_in[14];
    const float* mlp_b1 = (const float*)d_in[15];
    const float* mlp_w2 = (const float*)d_in[16];
    const float* mlp_b2 = (const float*)d_in[17];
    const float* norm_g = (const float*)d_in[18];
    const float* norm_b = (const float*)d_in[19];
    const float* head_w = (const float*)d_in[20];
    const float* head_b = (const float*)d_in[21];

    cudaFuncSetAttribute(attn_kernel,    cudaFuncAttributeMaxDynamicSharedMemorySize, ATTN_SMEM);
    cudaFuncSetAttribute(gemm_kernel<0>, cudaFuncAttributeMaxDynamicSharedMemorySize, GEMM_SMEM);
    cudaFuncSetAttribute(gemm_kernel<1>, cudaFuncAttributeMaxDynamicSharedMemorySize, GEMM_SMEM);
    cudaFuncSetAttribute(gemm_kernel<2>, cudaFuncAttributeMaxDynamicSharedMemorySize, GEMM_SMEM);

    float *px, *ph, *pq, *pa, *pm, *pc;
    cudaGetSymbolAddress((void**)&px, g_x);
    cudaGetSymbolAddress((void**)&ph, g_h);
    cudaGetSymbolAddress((void**)&pq, g_qkv);
    cudaGetSymbolAddress((void**)&pa, g_att);
    cudaGetSymbolAddress((void**)&pm, g_mlp);
    cudaGetSymbolAddress((void**)&pc, g_cls);

    seg_sum_kernel<<<kB, 256>>>(img, seg);
    embed_kernel<<<kM, 256>>>(w_fe, b_fe, cls_t, pos);

    const dim3 gQKV(kQKV / 128, (kM + 127) / 128);
    const dim3 gD  (kD   / 128, (kM + 127) / 128);
    const dim3 gMLP(kMLP / 128, (kM + 127) / 128);

    for (int l = 0; l < kL; l++) {
        ln_kernel<<<kM, 256>>>(px, ph, ln1_g + (size_t)l * kD, ln1_b + (size_t)l * kD, kD, kD);
        gemm_kernel<0><<<gQKV, 256, GEMM_SMEM>>>(ph, qkv_w + (size_t)l * kD * kQKV,
                                                 qkv_b + (size_t)l * kQKV, nullptr, pq,
                                                 kM, kQKV, kD);
        attn_kernel<<<kB * kNH, 256, ATTN_SMEM>>>();
        gemm_kernel<2><<<gD, 256, GEMM_SMEM>>>(pa, proj_w + (size_t)l * kD * kD,
                                               proj_b + (size_t)l * kD, px, px,
                                               kM, kD, kD);
        ln_kernel<<<kM, 256>>>(px, ph, ln2_g + (size_t)l * kD, ln2_b + (size_t)l * kD, kD, kD);
        gemm_kernel<1><<<gMLP, 256, GEMM_SMEM>>>(ph, mlp_w1 + (size_t)l * kD * kMLP,
                                                 mlp_b1 + (size_t)l * kMLP, nullptr, pm,
                                                 kM, kMLP, kD);
        gemm_kernel<2><<<gD, 256, GEMM_SMEM>>>(pm, mlp_w2 + (size_t)l * kMLP * kD,
                                               mlp_b2 + (size_t)l * kD, px, px,
                                               kM, kD, kMLP);
    }

    // Final LN on cls rows only (row b lives at x + b*257*768), then head.
    ln_kernel<<<kB, 256>>>(px, pc, norm_g, norm_b, (long)kN * kD, (long)kD);
    head_kernel<<<dim3((kNC + 255) / 256, kB), 256>>>(head_w, head_b, (float*)d_out);
}